// round 3
// baseline (speedup 1.0000x reference)
#include <cuda_runtime.h>

// ---------------------------------------------------------------------------
// 2-layer LSTM (H=51), B=4096, T=1000 + 100 autoregressive steps.
// Each of 128 blocks owns NB=32 batch elements; all 1100 steps run with
// weights + state in shared memory.
//
// GEMM: 8(g) x 8(e) register tiles, k-split across 2 groups of 104 threads
// (partials Gp[0], Gp[1] summed in the cell-update phase), packed
// fma.rn.f32x2 math. S[k][e] / W[k][g] are k-major; float4 shared loads.
// ---------------------------------------------------------------------------

#define H       51
#define R4      204          // 4*H gate rows
#define RP      208          // padded gate rows (mult of 8)
#define TSTEPS  1000
#define NTOT    1100
#define BATCH   4096
#define NB      32           // batch elements per block
#define NBLK    128          // 4096 / 32
#define NTH     256
#define K1      52           // layer1 k: 51 h1 + 1 x
#define K2      104          // layer2 k: 51 h1 + pad + 51 h2 + pad
#define K1H     26           // k per group, GEMM1
#define K2H     52           // k per group, GEMM2
#define GT      26           // g-tiles (RP/8)
#define ET      4            // e-tiles (NB/8)
#define GRPTH   104          // GT*ET threads per k-group
#define NGEMM   208          // 2 * GRPTH
#define CELLS   (H * NB)     // 1632 cell updates per layer

typedef unsigned long long ull;

// Transposed input: x_T[t][b]
__device__ float g_xT[TSTEPS * BATCH];

struct Smem {
    float W1[K1][RP];       // rows 0..50: Whh1^T, row 51: Wih1
    float W2[K2][RP];       // 0..50: Wih2^T, 51: 0, 52..102: Whh2^T, 103: 0
    float S[K2][NB];        // 0..50: h1, 51: x, 52..102: h2, 103: 0
    float Gp[2][RP][NB];    // per-k-group partial gate pre-activations
    float c1[H][NB];
    float c2[H][NB];
    float bs1[R4];          // b_ih1 + b_hh1
    float bs2[R4];          // b_ih2 + b_hh2
    float wlin[H];
    float outbuf[NB];       // last output (feeds x in future phase)
    float blin;
};

__device__ __forceinline__ float sigf(float x) {
    return 1.0f / (1.0f + __expf(-x));
}
__device__ __forceinline__ float tanh_f(float x) {
    float e = __expf(-2.0f * fabsf(x));
    float t = (1.0f - e) / (1.0f + e);
    return copysignf(t, x);
}

__device__ __forceinline__ ull packxy(float x, float y) {
    ull r; asm("mov.b64 %0, {%1, %2};" : "=l"(r) : "f"(x), "f"(y)); return r;
}
__device__ __forceinline__ ull pack2(float w) {
    ull r; asm("mov.b64 %0, {%1, %1};" : "=l"(r) : "f"(w)); return r;
}
__device__ __forceinline__ void fma2(ull& d, ull a, ull b) {
    asm("fma.rn.f32x2 %0, %1, %2, %0;" : "+l"(d) : "l"(a), "l"(b));
}
__device__ __forceinline__ float2 unpk(ull v) {
    float2 f; asm("mov.b64 {%0, %1}, %2;" : "=f"(f.x), "=f"(f.y) : "l"(v)); return f;
}

__global__ void prep_kernel(const float* __restrict__ in) {
    int stride = gridDim.x * blockDim.x;
    for (int idx = blockIdx.x * blockDim.x + threadIdx.x;
         idx < BATCH * TSTEPS; idx += stride) {
        int b = idx / TSTEPS;
        int t = idx - b * TSTEPS;
        g_xT[t * BATCH + b] = in[idx];
    }
}

// One k-slab GEMM: acc[8 g][4 f32x2-e] += W[k][g0..g0+7] (x) S[k][e0..e0+7]
template <int KH>
__device__ __forceinline__ void gemm_slab(const float (*W)[RP], const float (*S)[NB],
                                          float (*Gout)[NB], int kbase,
                                          int g0, int e0) {
    ull acc[8][4];
    #pragma unroll
    for (int i = 0; i < 8; ++i)
        #pragma unroll
        for (int j = 0; j < 4; ++j) acc[i][j] = 0ull;

    #pragma unroll 2
    for (int kk = 0; kk < KH; ++kk) {
        int k = kbase + kk;
        float4 h0 = *reinterpret_cast<const float4*>(&S[k][e0]);
        float4 h1 = *reinterpret_cast<const float4*>(&S[k][e0 + 4]);
        float4 w0 = *reinterpret_cast<const float4*>(&W[k][g0]);
        float4 w1 = *reinterpret_cast<const float4*>(&W[k][g0 + 4]);
        ull hp0 = packxy(h0.x, h0.y), hp1 = packxy(h0.z, h0.w);
        ull hp2 = packxy(h1.x, h1.y), hp3 = packxy(h1.z, h1.w);
        float wf[8] = {w0.x, w0.y, w0.z, w0.w, w1.x, w1.y, w1.z, w1.w};
        #pragma unroll
        for (int i = 0; i < 8; ++i) {
            ull wp = pack2(wf[i]);
            fma2(acc[i][0], wp, hp0);
            fma2(acc[i][1], wp, hp1);
            fma2(acc[i][2], wp, hp2);
            fma2(acc[i][3], wp, hp3);
        }
    }
    #pragma unroll
    for (int i = 0; i < 8; ++i) {
        float2 a0 = unpk(acc[i][0]), a1 = unpk(acc[i][1]);
        float2 a2 = unpk(acc[i][2]), a3 = unpk(acc[i][3]);
        float4 v0 = {a0.x, a0.y, a1.x, a1.y};
        float4 v1 = {a2.x, a2.y, a3.x, a3.y};
        *reinterpret_cast<float4*>(&Gout[g0 + i][e0])     = v0;
        *reinterpret_cast<float4*>(&Gout[g0 + i][e0 + 4]) = v1;
    }
}

__global__ __launch_bounds__(NTH, 1)
void lstm_kernel(const float* __restrict__ Wih1, const float* __restrict__ Whh1,
                 const float* __restrict__ bih1, const float* __restrict__ bhh1,
                 const float* __restrict__ Wih2, const float* __restrict__ Whh2,
                 const float* __restrict__ bih2, const float* __restrict__ bhh2,
                 const float* __restrict__ Wlin, const float* __restrict__ blin,
                 float* __restrict__ out) {
    extern __shared__ unsigned char smraw[];
    Smem* sm = reinterpret_cast<Smem*>(smraw);
    const int tid = threadIdx.x;
    const int b0  = blockIdx.x * NB;

    // ---- one-time init ----
    for (int idx = tid; idx < K1 * RP; idx += NTH) {
        int k = idx / RP, g = idx - (idx / RP) * RP;
        float v = 0.0f;
        if (g < R4) v = (k < H) ? Whh1[g * H + k] : Wih1[g];
        sm->W1[k][g] = v;
    }
    for (int idx = tid; idx < K2 * RP; idx += NTH) {
        int k = idx / RP, g = idx - (idx / RP) * RP;
        float v = 0.0f;
        if (g < R4) {
            if (k < H)                      v = Wih2[g * H + k];
            else if (k >= 52 && k < 52 + H) v = Whh2[g * H + (k - 52)];
        }
        sm->W2[k][g] = v;
    }
    for (int idx = tid; idx < R4; idx += NTH) {
        sm->bs1[idx] = bih1[idx] + bhh1[idx];
        sm->bs2[idx] = bih2[idx] + bhh2[idx];
    }
    for (int idx = tid; idx < H; idx += NTH) sm->wlin[idx] = Wlin[idx];
    if (tid == 0) sm->blin = blin[0];
    for (int idx = tid; idx < K2 * NB; idx += NTH) (&sm->S[0][0])[idx] = 0.0f;
    for (int idx = tid; idx < H * NB; idx += NTH) {
        (&sm->c1[0][0])[idx] = 0.0f;
        (&sm->c2[0][0])[idx] = 0.0f;
    }
    __syncthreads();

    const bool gemm_active = (tid < NGEMM);
    const int  grp = tid / GRPTH;                 // 0 or 1 (k-group)
    const int  gid = tid - grp * GRPTH;           // 0..103
    const int  e0  = (gid % ET) * 8;              // 0,8,16,24
    const int  g0  = (gid / ET) * 8;              // 0,8,...,200

    for (int t = 0; t < NTOT; ++t) {
        // ---- stage x(t) into S row 51 ----
        if (tid < NB) {
            float x = (t < TSTEPS) ? g_xT[t * BATCH + b0 + tid] : sm->outbuf[tid];
            sm->S[H][tid] = x;
        }
        __syncthreads();

        // ---- GEMM1 (k halves per group) ----
        if (gemm_active)
            gemm_slab<K1H>(sm->W1, sm->S, sm->Gp[grp], grp * K1H, g0, e0);
        __syncthreads();

        // ---- cell update layer 1: h1 -> S rows 0..50 ----
        for (int c = tid; c < CELLS; c += NTH) {
            int k = c / NB, e = c - (c / NB) * NB;
            float gi = sm->Gp[0][k      ][e] + sm->Gp[1][k      ][e] + sm->bs1[k];
            float gf = sm->Gp[0][H   + k][e] + sm->Gp[1][H   + k][e] + sm->bs1[H   + k];
            float gg = sm->Gp[0][2*H + k][e] + sm->Gp[1][2*H + k][e] + sm->bs1[2*H + k];
            float go = sm->Gp[0][3*H + k][e] + sm->Gp[1][3*H + k][e] + sm->bs1[3*H + k];
            float cc = sm->c1[k][e];
            float cn = sigf(gf) * cc + sigf(gi) * tanh_f(gg);
            float hn = sigf(go) * tanh_f(cn);
            sm->c1[k][e] = cn;
            sm->S[k][e]  = hn;
        }
        __syncthreads();

        // ---- GEMM2 ----
        if (gemm_active)
            gemm_slab<K2H>(sm->W2, sm->S, sm->Gp[grp], grp * K2H, g0, e0);
        __syncthreads();

        // ---- cell update layer 2: h2 -> S rows 52..102 ----
        for (int c = tid; c < CELLS; c += NTH) {
            int k = c / NB, e = c - (c / NB) * NB;
            float gi = sm->Gp[0][k      ][e] + sm->Gp[1][k      ][e] + sm->bs2[k];
            float gf = sm->Gp[0][H   + k][e] + sm->Gp[1][H   + k][e] + sm->bs2[H   + k];
            float gg = sm->Gp[0][2*H + k][e] + sm->Gp[1][2*H + k][e] + sm->bs2[2*H + k];
            float go = sm->Gp[0][3*H + k][e] + sm->Gp[1][3*H + k][e] + sm->bs2[3*H + k];
            float cc = sm->c2[k][e];
            float cn = sigf(gf) * cc + sigf(gi) * tanh_f(gg);
            float hn = sigf(go) * tanh_f(cn);
            sm->c2[k][e]     = cn;
            sm->S[52 + k][e] = hn;
        }
        __syncthreads();

        // ---- output: out[e] = h2[e] . wlin + blin ----
        if (tid < NB) {
            float acc = sm->blin;
            #pragma unroll 4
            for (int k = 0; k < H; ++k) acc += sm->S[52 + k][tid] * sm->wlin[k];
            sm->outbuf[tid] = acc;
            out[(b0 + tid) * NTOT + t] = acc;
        }
        __syncthreads();   // protects outbuf / Gp reuse across iterations
    }
}

extern "C" void kernel_launch(void* const* d_in, const int* in_sizes, int n_in,
                              void* d_out, int out_size) {
    const float* inputs = (const float*)d_in[0];
    const float* Wih1   = (const float*)d_in[1];
    const float* Whh1   = (const float*)d_in[2];
    const float* bih1   = (const float*)d_in[3];
    const float* bhh1   = (const float*)d_in[4];
    const float* Wih2   = (const float*)d_in[5];
    const float* Whh2   = (const float*)d_in[6];
    const float* bih2   = (const float*)d_in[7];
    const float* bhh2   = (const float*)d_in[8];
    const float* Wlin   = (const float*)d_in[9];
    const float* blin   = (const float*)d_in[10];
    // d_in[11] = future (hardcoded 100)

    cudaFuncSetAttribute(lstm_kernel,
                         cudaFuncAttributeMaxDynamicSharedMemorySize,
                         (int)sizeof(Smem));

    prep_kernel<<<256, 256>>>(inputs);
    lstm_kernel<<<NBLK, NTH, sizeof(Smem)>>>(Wih1, Whh1, bih1, bhh1,
                                             Wih2, Whh2, bih2, bhh2,
                                             Wlin, blin, (float*)d_out);
}